// round 16
// baseline (speedup 1.0000x reference)
#include <cuda_runtime.h>
#include <stdint.h>

#define NOPP 3
#define NS   80
#define NA   6
#define DD   512
#define RB   4      // batch rows per fused block
#define TPB  160    // 5 warps: 4 rows x 40 sample-threads; 2 samples/thread

// ---------------- device scratch ----------------
__device__ float g_wt[24 * DD];           // column-major weights (48 KB, L2-resident)
__device__ unsigned long long g_entacc;
__device__ unsigned int g_entticket;

// ---------------- threefry2x32, key=(0,42), counter=(0,i); out = x0^x1 ----------------
__device__ __forceinline__ uint32_t tf_fold(uint32_t c1)
{
    const uint32_t KS1 = 42u;
    const uint32_t KS2 = 0x1BD11BDAu ^ 42u;   // ks0 = 0
    uint32_t x0 = 0u, x1 = c1 + KS1;
#define TFR(r) { x0 += x1; x1 = __funnelshift_l(x1, x1, (r)); x1 ^= x0; }
    TFR(13) TFR(15) TFR(26) TFR(6)
    x0 += KS1; x1 += KS2 + 1u;
    TFR(17) TFR(29) TFR(16) TFR(24)
    x0 += KS2; x1 += 2u;
    TFR(13) TFR(15) TFR(26) TFR(6)
    x1 += KS1 + 3u;
    TFR(17) TFR(29) TFR(16) TFR(24)
    x0 += KS1; x1 += KS2 + 4u;
    TFR(13) TFR(15) TFR(26) TFR(6)
    x0 += KS2; x1 += 5u;
#undef TFR
    return x0 ^ x1;
}

// ---------------- kT: transpose weights (48 blocks x 256 = 1 elem/thread) -------------
__global__ void __launch_bounds__(256) kT(const float* __restrict__ Wopp,
                                          const float* __restrict__ W)
{
    int i = blockIdx.x * 256 + threadIdx.x;       // 0 .. 12287
    if (i < NOPP * DD * NA) {                     // 9216 Wopp elements
        int k = i / (DD * NA), r = i % (DD * NA);
        int d = r / NA, a = r % NA;
        g_wt[(k * NA + a) * DD + d] = Wopp[i];
    } else {                                      // 3072 W[:512] elements
        int j = i - NOPP * DD * NA;
        int d = j / NA, a = j % NA;
        g_wt[(18 + a) * DD + d] = W[j];
    }
}

// ---------------- kf: fused GEMM + softmax tables (smem) + sampler ----------------
__global__ void __launch_bounds__(TPB, 7) kf(
    const float* __restrict__ x, const float* __restrict__ bopp,
    const float* __restrict__ W, const float* __restrict__ bias,
    float* __restrict__ out, int B, int out_size)
{
    __shared__ float xs[RB * DD];            // 8 KB
    __shared__ float vals[RB][25];
    __shared__ float einv_s[RB][20];
    __shared__ float dist_s[RB][20];
    __shared__ float base_s[RB][8];
    __shared__ float W2s[18 * 8];
    __shared__ float entkb[RB * 3];
    __shared__ float pool[7 * TPB];          // 4.5 KB

    int tid  = threadIdx.x;
    int warp = tid >> 5;
    int lane = tid & 31;
    int b0   = blockIdx.x * RB;

    if (tid < 18 * NA) W2s[(tid / 6) * 8 + (tid % 6)] = W[DD * NA + tid];

    // ---- stage x rows (float4 coalesced) ----
    if (b0 + RB <= B) {
        const float4* x4 = reinterpret_cast<const float4*>(x + (size_t)b0 * DD);
        float4* xs4 = reinterpret_cast<float4*>(xs);
        for (int i = tid; i < RB * DD / 4; i += TPB) xs4[i] = x4[i];
    } else {
        for (int i = tid; i < RB * DD; i += TPB) {
            int r = i / DD;
            xs[i] = (b0 + r < B) ? x[(size_t)(b0 + r) * DD + (i % DD)] : 0.0f;
        }
    }
    __syncthreads();

    // ---- GEMM: warp w handles cols c = w, w+5, ... ; 4-row reuse per weight reg ----
    for (int c = warp; c < 24; c += 5) {
        float wreg[16];
        const float* wp = g_wt + (size_t)c * DD + lane;
#pragma unroll
        for (int j = 0; j < 16; j++) wreg[j] = wp[32 * j];
        float a0 = 0.f, a1 = 0.f, a2 = 0.f, a3 = 0.f;
#pragma unroll
        for (int j = 0; j < 16; j++) {
            int d = lane + 32 * j;
            float w = wreg[j];
            a0 = fmaf(xs[0 * DD + d], w, a0);
            a1 = fmaf(xs[1 * DD + d], w, a1);
            a2 = fmaf(xs[2 * DD + d], w, a2);
            a3 = fmaf(xs[3 * DD + d], w, a3);
        }
#pragma unroll
        for (int off = 16; off; off >>= 1) {
            a0 += __shfl_down_sync(0xffffffffu, a0, off);
            a1 += __shfl_down_sync(0xffffffffu, a1, off);
            a2 += __shfl_down_sync(0xffffffffu, a2, off);
            a3 += __shfl_down_sync(0xffffffffu, a3, off);
        }
        if (lane == 0) {
            vals[0][c] = a0; vals[1][c] = a1; vals[2][c] = a2; vals[3][c] = a3;
        }
    }
    __syncthreads();

    // ---- postprocess: softmax/einv/dist/entropy + agent base, all in smem ----
    for (int i = tid; i < RB * 3; i += TPB) {
        int r = i / 3, k = i % 3, b = b0 + r;
        if (b < B) {
            float l[NA], m = -1e30f;
#pragma unroll
            for (int a = 0; a < NA; a++) {
                l[a] = vals[r][k * 6 + a] + bopp[k * 6 + a];
                m = fmaxf(m, l[a]);
            }
            float e[NA], S = 0.0f;
#pragma unroll
            for (int a = 0; a < NA; a++) { e[a] = expf(l[a] - m); S += e[a]; }
            float logS = logf(S);
            float ent = 0.0f;
            size_t distoff = (size_t)B * NA + ((size_t)k * B + b) * NA;
#pragma unroll
            for (int a = 0; a < NA; a++) {
                float d = e[a] / S;
                dist_s[r][k * 6 + a] = d;
                einv_s[r][k * 6 + a] = expf(-l[a]);
                ent -= d * ((l[a] - m) - logS);
                if (out_size >= B * 24) out[distoff + a] = d;
            }
            entkb[i] = ent;
        } else entkb[i] = 0.0f;
    }
    for (int i = tid; i < RB * 6; i += TPB) {
        int r = i / 6, a = i % 6, b = b0 + r;
        if (b < B) base_s[r][a] = vals[r][18 + a] + bias[a];
    }
    __syncthreads();

    // ---- entropy: fixed-point atomic + last-block ticket (deterministic) ----
    if (tid == 0) {
        float part = 0.0f;
        for (int i = 0; i < RB * 3; i++) part += entkb[i];
        unsigned long long q =
            (unsigned long long)__double2ll_rn((double)part * 2199023255552.0); // 2^41
        atomicAdd(&g_entacc, q);
        __threadfence();
        unsigned int old = atomicAdd(&g_entticket, 1u);
        if (old == gridDim.x - 1) {
            unsigned long long tot = atomicExch(&g_entacc, 0ull);
            atomicExch(&g_entticket, 0u);
            if (out_size >= B * 24 + 1)
                out[(size_t)B * 24] =
                    (float)((double)tot * (1.0 / 2199023255552.0) / (3.0 * (double)B));
        }
    }

    // ---- sampling: 4 rows x 40 threads, 2 samples/thread (R9-proven) ----
    int r = tid / 40;
    int j = tid - r * 40;
    int b = b0 + r;

    float num[NA] = {0, 0, 0, 0, 0, 0}, den = 0.0f;
    if (b < B) {
        float einv[18];
#pragma unroll
        for (int i = 0; i < 18; i++) einv[i] = einv_s[r][i];

#pragma unroll
        for (int sp = 0; sp < 2; sp++) {
            int s = j + sp * 40;
            float p1 = 1.0f, l[NA];
#pragma unroll
            for (int a = 0; a < NA; a++) l[a] = base_s[r][a];
#pragma unroll
            for (int k = 0; k < 3; k++) {
                uint32_t c0 = (uint32_t)(((k * NS + s) * B + b) * NA);
                uint32_t mp = 0xFFFFFFFFu;
#pragma unroll
                for (int a = 0; a < NA; a++) {  // 6 independent hash chains -> ILP
                    uint32_t bits = tf_fold(c0 + (uint32_t)a);
                    // u = f-1 in [0,1); v = log2(u)*einv (<=0). argmin t*einv
                    // == argmax v; negative-float uint order is reversed, so
                    // umin picks max v; ties pick the lowest action.
                    float f = __uint_as_float((bits >> 9) | 0x3f800000u) - 1.0f;
                    float v = __log2f(f) * einv[k * 6 + a];
                    uint32_t pv = (__float_as_uint(v) & 0xFFFFFFF8u) | (uint32_t)a;
                    mp = (mp < pv) ? mp : pv;
                }
                int amin = (int)(mp & 7u);
                p1 *= dist_s[r][k * 6 + amin];
#pragma unroll
                for (int a = 0; a < NA; a++) l[a] += W2s[(k * 6 + amin) * 8 + a];
            }
            float m = l[0];
#pragma unroll
            for (int a = 1; a < NA; a++) m = fmaxf(m, l[a]);
            float e[NA], S = 0.0f;
#pragma unroll
            for (int a = 0; a < NA; a++) { e[a] = __expf(l[a] - m); S += e[a]; }
            float w = p1 / S;
#pragma unroll
            for (int a = 0; a < NA; a++) num[a] = fmaf(w, e[a], num[a]);
            den += p1;
        }
    }

    // ---- deterministic combine: smem stage + per-row warp tree ----
#pragma unroll
    for (int a = 0; a < NA; a++) pool[a * TPB + tid] = num[a];
    pool[6 * TPB + tid] = den;
    __syncthreads();

    if (warp < RB) {
        int bb = b0 + warp;
        if (bb < B) {
            float res[7];
#pragma unroll
            for (int i = 0; i < 7; i++) {
                int base = i * TPB + warp * 40;
                float p = pool[base + lane];
                if (lane < 8) p += pool[base + 32 + lane];
#pragma unroll
                for (int off = 16; off; off >>= 1)
                    p += __shfl_down_sync(0xffffffffu, p, off);
                res[i] = p;
            }
            if (lane == 0) {
                float inv = 1.0f / res[6];
#pragma unroll
                for (int a = 0; a < NA; a++)
                    out[(size_t)bb * NA + a] = res[a] * inv;
            }
        }
    }
}

// ---------------- launch ----------------
extern "C" void kernel_launch(void* const* d_in, const int* in_sizes, int n_in,
                              void* d_out, int out_size)
{
    const float* x    = (const float*)d_in[0];
    const float* Wopp = (const float*)d_in[1];
    const float* bopp = (const float*)d_in[2];
    const float* W    = (const float*)d_in[3];
    const float* bias = (const float*)d_in[4];
    float* out = (float*)d_out;

    int D = in_sizes[1] / (NOPP * NA);   // 512
    int B = in_sizes[0] / D;             // 4096
    if (B > 4096) B = 4096;

    kT<<<48, 256>>>(Wopp, W);            // 12288 threads, 1 element each
    kf<<<(B + RB - 1) / RB, TPB>>>(x, bopp, W, bias, out, B, out_size);
}

// round 17
// speedup vs baseline: 1.0528x; 1.0528x over previous
#include <cuda_runtime.h>
#include <stdint.h>

#define NOPP 3
#define NS   80
#define NA   6
#define DD   512
#define RB   8      // batch rows per fused block
#define TPB  320    // 10 warps: 8 rows x 40 sample-threads; 2 samples/thread

// ---------------- device scratch ----------------
__device__ float g_wt[24 * DD];           // column-major weights (48 KB, L2-resident)
__device__ unsigned long long g_entacc;
__device__ unsigned int g_entticket;

// ---------------- threefry2x32, key=(0,42), counter=(0,i); out = x0^x1 ----------------
__device__ __forceinline__ uint32_t tf_fold(uint32_t c1)
{
    const uint32_t KS1 = 42u;
    const uint32_t KS2 = 0x1BD11BDAu ^ 42u;   // ks0 = 0
    uint32_t x0 = 0u, x1 = c1 + KS1;
#define TFR(r) { x0 += x1; x1 = __funnelshift_l(x1, x1, (r)); x1 ^= x0; }
    TFR(13) TFR(15) TFR(26) TFR(6)
    x0 += KS1; x1 += KS2 + 1u;
    TFR(17) TFR(29) TFR(16) TFR(24)
    x0 += KS2; x1 += 2u;
    TFR(13) TFR(15) TFR(26) TFR(6)
    x1 += KS1 + 3u;
    TFR(17) TFR(29) TFR(16) TFR(24)
    x0 += KS1; x1 += KS2 + 4u;
    TFR(13) TFR(15) TFR(26) TFR(6)
    x0 += KS2; x1 += 5u;
#undef TFR
    return x0 ^ x1;
}

// ---------------- kT: transpose weights (48 blocks x 256 = 1 elem/thread) -------------
__global__ void __launch_bounds__(256) kT(const float* __restrict__ Wopp,
                                          const float* __restrict__ W)
{
    int i = blockIdx.x * 256 + threadIdx.x;       // 0 .. 12287
    if (i < NOPP * DD * NA) {                     // 9216 Wopp elements
        int k = i / (DD * NA), r = i % (DD * NA);
        int d = r / NA, a = r % NA;
        g_wt[(k * NA + a) * DD + d] = Wopp[i];
    } else {                                      // 3072 W[:512] elements
        int j = i - NOPP * DD * NA;
        int d = j / NA, a = j % NA;
        g_wt[(18 + a) * DD + d] = W[j];
    }
}

// ---------------- kf: fused GEMM (coalesced g_wt) + smem tables + sampler ------------
__global__ void __launch_bounds__(TPB, 3) kf(
    const float* __restrict__ x, const float* __restrict__ bopp,
    const float* __restrict__ W, const float* __restrict__ bias,
    float* __restrict__ out, int B, int out_size)
{
    __shared__ float xs[RB * DD];            // 16 KB
    __shared__ float vals[RB][25];
    __shared__ float einv_s[RB][20];
    __shared__ float dist_s[RB][20];
    __shared__ float base_s[RB][8];
    __shared__ float W2s[18 * 8];
    __shared__ float entkb[RB * 3];
    __shared__ float pool[7 * TPB];          // 9 KB

    int tid  = threadIdx.x;
    int warp = tid >> 5;
    int lane = tid & 31;
    int b0   = blockIdx.x * RB;

    if (tid < 18 * NA) W2s[(tid / 6) * 8 + (tid % 6)] = W[DD * NA + tid];

    // ---- stage x rows (float4 coalesced) ----
    if (b0 + RB <= B) {
        const float4* x4 = reinterpret_cast<const float4*>(x + (size_t)b0 * DD);
        float4* xs4 = reinterpret_cast<float4*>(xs);
        for (int i = tid; i < RB * DD / 4; i += TPB) xs4[i] = x4[i];
    } else {
        for (int i = tid; i < RB * DD; i += TPB) {
            int r = i / DD;
            xs[i] = (b0 + r < B) ? x[(size_t)(b0 + r) * DD + (i % DD)] : 0.0f;
        }
    }

    // ---- GEMM: warps 0..7 own cols 3w..3w+2, fully coalesced from g_wt ----
    if (warp < 8) {
        float w0[16], w1[16], w2[16];
        int c = 3 * warp;
        const float* s0 = g_wt + (size_t)(c + 0) * DD + lane;
        const float* s1 = g_wt + (size_t)(c + 1) * DD + lane;
        const float* s2 = g_wt + (size_t)(c + 2) * DD + lane;
#pragma unroll
        for (int j = 0; j < 16; j++) {
            w0[j] = s0[32 * j]; w1[j] = s1[32 * j]; w2[j] = s2[32 * j];
        }
        __syncthreads();                     // xs staged
        for (int r = 0; r < RB; r++) {
            const float* xr = xs + r * DD + lane;
            float a0 = 0.f, a1 = 0.f, a2 = 0.f;
#pragma unroll
            for (int j = 0; j < 16; j++) {
                float xv = xr[32 * j];
                a0 = fmaf(xv, w0[j], a0);
                a1 = fmaf(xv, w1[j], a1);
                a2 = fmaf(xv, w2[j], a2);
            }
#pragma unroll
            for (int off = 16; off; off >>= 1) {
                a0 += __shfl_down_sync(0xffffffffu, a0, off);
                a1 += __shfl_down_sync(0xffffffffu, a1, off);
                a2 += __shfl_down_sync(0xffffffffu, a2, off);
            }
            if (lane == 0) {
                vals[r][c + 0] = a0;
                vals[r][c + 1] = a1;
                vals[r][c + 2] = a2;
            }
        }
    } else {
        __syncthreads();                     // matching barrier (warps 8,9)
    }
    __syncthreads();

    // ---- postprocess: softmax/einv/dist/entropy + agent base, all in smem ----
    for (int i = tid; i < RB * 3; i += TPB) {
        int r = i / 3, k = i % 3, b = b0 + r;
        if (b < B) {
            float l[NA], m = -1e30f;
#pragma unroll
            for (int a = 0; a < NA; a++) {
                l[a] = vals[r][k * 6 + a] + bopp[k * 6 + a];
                m = fmaxf(m, l[a]);
            }
            float e[NA], S = 0.0f;
#pragma unroll
            for (int a = 0; a < NA; a++) { e[a] = expf(l[a] - m); S += e[a]; }
            float logS = logf(S);
            float ent = 0.0f;
            size_t distoff = (size_t)B * NA + ((size_t)k * B + b) * NA;
#pragma unroll
            for (int a = 0; a < NA; a++) {
                float d = e[a] / S;
                dist_s[r][k * 6 + a] = d;
                einv_s[r][k * 6 + a] = expf(-l[a]);
                ent -= d * ((l[a] - m) - logS);
                if (out_size >= B * 24) out[distoff + a] = d;
            }
            entkb[i] = ent;
        } else entkb[i] = 0.0f;
    }
    for (int i = tid; i < RB * 6; i += TPB) {
        int r = i / 6, a = i % 6, b = b0 + r;
        if (b < B) base_s[r][a] = vals[r][18 + a] + bias[a];
    }
    __syncthreads();

    // ---- entropy: fixed-point atomic + last-block ticket (deterministic) ----
    if (tid == 0) {
        float part = 0.0f;
        for (int i = 0; i < RB * 3; i++) part += entkb[i];
        unsigned long long q =
            (unsigned long long)__double2ll_rn((double)part * 2199023255552.0); // 2^41
        atomicAdd(&g_entacc, q);
        __threadfence();
        unsigned int old = atomicAdd(&g_entticket, 1u);
        if (old == gridDim.x - 1) {
            unsigned long long tot = atomicExch(&g_entacc, 0ull);
            atomicExch(&g_entticket, 0u);
            if (out_size >= B * 24 + 1)
                out[(size_t)B * 24] =
                    (float)((double)tot * (1.0 / 2199023255552.0) / (3.0 * (double)B));
        }
    }

    // ---- sampling: 8 rows x 40 threads, 2 samples/thread (R9-proven shape) ----
    int r = tid / 40;
    int j = tid - r * 40;
    int b = b0 + r;

    float num[NA] = {0, 0, 0, 0, 0, 0}, den = 0.0f;
    if (b < B) {
        float einv[18];
#pragma unroll
        for (int i = 0; i < 18; i++) einv[i] = einv_s[r][i];

#pragma unroll
        for (int sp = 0; sp < 2; sp++) {
            int s = j + sp * 40;
            float p1 = 1.0f, l[NA];
#pragma unroll
            for (int a = 0; a < NA; a++) l[a] = base_s[r][a];
#pragma unroll
            for (int k = 0; k < 3; k++) {
                uint32_t c0 = (uint32_t)(((k * NS + s) * B + b) * NA);
                uint32_t mp = 0xFFFFFFFFu;
#pragma unroll
                for (int a = 0; a < NA; a++) {  // 6 independent hash chains -> ILP
                    uint32_t bits = tf_fold(c0 + (uint32_t)a);
                    // u = f-1 in [0,1); v = log2(u)*einv (<=0). argmin t*einv
                    // == argmax v; negative-float uint order is reversed, so
                    // umin picks max v; ties pick the lowest action.
                    float f = __uint_as_float((bits >> 9) | 0x3f800000u) - 1.0f;
                    float v = __log2f(f) * einv[k * 6 + a];
                    uint32_t pv = (__float_as_uint(v) & 0xFFFFFFF8u) | (uint32_t)a;
                    mp = (mp < pv) ? mp : pv;
                }
                int amin = (int)(mp & 7u);
                p1 *= dist_s[r][k * 6 + amin];
#pragma unroll
                for (int a = 0; a < NA; a++) l[a] += W2s[(k * 6 + amin) * 8 + a];
            }
            float m = l[0];
#pragma unroll
            for (int a = 1; a < NA; a++) m = fmaxf(m, l[a]);
            float e[NA], S = 0.0f;
#pragma unroll
            for (int a = 0; a < NA; a++) { e[a] = __expf(l[a] - m); S += e[a]; }
            float w = p1 / S;
#pragma unroll
            for (int a = 0; a < NA; a++) num[a] = fmaf(w, e[a], num[a]);
            den += p1;
        }
    }

    // ---- deterministic combine: smem stage + per-row warp tree ----
#pragma unroll
    for (int a = 0; a < NA; a++) pool[a * TPB + tid] = num[a];
    pool[6 * TPB + tid] = den;
    __syncthreads();

    if (warp < RB) {
        int bb = b0 + warp;
        if (bb < B) {
            float res[7];
#pragma unroll
            for (int i = 0; i < 7; i++) {
                int base = i * TPB + warp * 40;
                float p = pool[base + lane];
                if (lane < 8) p += pool[base + 32 + lane];
#pragma unroll
                for (int off = 16; off; off >>= 1)
                    p += __shfl_down_sync(0xffffffffu, p, off);
                res[i] = p;
            }
            if (lane == 0) {
                float inv = 1.0f / res[6];
#pragma unroll
                for (int a = 0; a < NA; a++)
                    out[(size_t)bb * NA + a] = res[a] * inv;
            }
        }
    }
}

// ---------------- launch ----------------
extern "C" void kernel_launch(void* const* d_in, const int* in_sizes, int n_in,
                              void* d_out, int out_size)
{
    const float* x    = (const float*)d_in[0];
    const float* Wopp = (const float*)d_in[1];
    const float* bopp = (const float*)d_in[2];
    const float* W    = (const float*)d_in[3];
    const float* bias = (const float*)d_in[4];
    float* out = (float*)d_out;

    int D = in_sizes[1] / (NOPP * NA);   // 512
    int B = in_sizes[0] / D;             // 4096
    if (B > 4096) B = 4096;

    kT<<<48, 256>>>(Wopp, W);            // 12288 threads, 1 element each
    kf<<<(B + RB - 1) / RB, TPB>>>(x, bopp, W, bias, out, B, out_size);
}